// round 14
// baseline (speedup 1.0000x reference)
#include <cuda_runtime.h>
#include <cuda_bf16.h>
#include <cstdint>

#define DD    16
#define HH    64
#define WW    64
#define PTOT  (DD*HH*WW)      // 65536
#define C3    21
#define LOG2E 1.4426950408889634f

// scratch: rows 0-63 = q, 64-127 = k, 128-191 = v
__device__ float g_qkv[192 * PTOT];

// fragment-major operands for m16n8k16 row.col
__device__ __align__(16) uint4 g_xhf[(PTOT / 16) * 4 * 32];
__device__ __align__(16) uint4 g_xlf[(PTOT / 16) * 4 * 32];
__device__ __align__(16) uint2 g_whf[24 * 4 * 32];
__device__ __align__(16) uint2 g_wlf[24 * 4 * 32];

__device__ __forceinline__ float ex2(float x) {
    float r;
    asm("ex2.approx.ftz.f32 %0, %1;" : "=f"(r) : "f"(x));
    return r;
}

__device__ __forceinline__ unsigned int packbf(float a, float b) {
    __nv_bfloat162 h = __floats2bfloat162_rn(a, b);
    return *(unsigned int*)&h;
}

// ---------------------------------------------------------------------------
// Prep A: x (fp32 [ci][pos]) -> fragment-major bf16 hi/lo (as round 13).
// ---------------------------------------------------------------------------
__global__ void __launch_bounds__(256)
prep_x_kernel(const float* __restrict__ x) {
    __shared__ float tile[64 * 65];
    const int tid = threadIdx.x;
    const int p0  = blockIdx.x * 64;

#pragma unroll
    for (int i = 0; i < 16; i++) {
        int j  = i * 256 + tid;
        int ci = j >> 6, p = j & 63;
        tile[ci * 65 + p] = x[ci * PTOT + p0 + p];
    }
    __syncthreads();

#pragma unroll
    for (int i = 0; i < 2; i++) {
        int j    = i * 256 + tid;
        int lane = j & 31;
        int k    = (j >> 5) & 3;
        int lt   = j >> 7;
        int r    = lane >> 2;
        int kc   = k * 16 + (lane & 3) * 2;
        int pa   = lt * 16 + r;
        int pb   = pa + 8;

        float v00 = tile[kc * 65 + pa],       v01 = tile[(kc + 1) * 65 + pa];
        float v10 = tile[kc * 65 + pb],       v11 = tile[(kc + 1) * 65 + pb];
        float v20 = tile[(kc + 8) * 65 + pa], v21 = tile[(kc + 9) * 65 + pa];
        float v30 = tile[(kc + 8) * 65 + pb], v31 = tile[(kc + 9) * 65 + pb];

        float h00 = __bfloat162float(__float2bfloat16(v00));
        float h01 = __bfloat162float(__float2bfloat16(v01));
        float h10 = __bfloat162float(__float2bfloat16(v10));
        float h11 = __bfloat162float(__float2bfloat16(v11));
        float h20 = __bfloat162float(__float2bfloat16(v20));
        float h21 = __bfloat162float(__float2bfloat16(v21));
        float h30 = __bfloat162float(__float2bfloat16(v30));
        float h31 = __bfloat162float(__float2bfloat16(v31));

        size_t idx = ((size_t)(p0 / 16 + lt) * 4 + k) * 32 + lane;
        g_xhf[idx] = make_uint4(packbf(h00, h01), packbf(h10, h11),
                                packbf(h20, h21), packbf(h30, h31));
        g_xlf[idx] = make_uint4(packbf(v00 - h00, v01 - h01),
                                packbf(v10 - h10, v11 - h11),
                                packbf(v20 - h20, v21 - h21),
                                packbf(v30 - h30, v31 - h31));
    }
}

// ---------------------------------------------------------------------------
// Prep B: W -> fragment-major bf16 hi/lo (as round 13).
// ---------------------------------------------------------------------------
__global__ void prep_w_kernel(const float* __restrict__ wq,
                              const float* __restrict__ wk,
                              const float* __restrict__ wv) {
    int j = blockIdx.x * 256 + threadIdx.x;
    if (j >= 24 * 4 * 32) return;
    int lane = j & 31;
    int k    = (j >> 5) & 3;
    int nt   = j >> 7;
    int c    = nt * 8 + (lane >> 2);
    int kc   = k * 16 + (lane & 3) * 2;

    const float* src;
    int cr = c;
    if (c < 64)       { src = wq; }
    else if (c < 128) { src = wk; cr = c - 64; }
    else              { src = wv; cr = c - 128; }

    float v00 = src[cr * 64 + kc],     v01 = src[cr * 64 + kc + 1];
    float v10 = src[cr * 64 + kc + 8], v11 = src[cr * 64 + kc + 9];

    float h00 = __bfloat162float(__float2bfloat16(v00));
    float h01 = __bfloat162float(__float2bfloat16(v01));
    float h10 = __bfloat162float(__float2bfloat16(v10));
    float h11 = __bfloat162float(__float2bfloat16(v11));

    g_whf[j] = make_uint2(packbf(h00, h01), packbf(h10, h11));
    g_wlf[j] = make_uint2(packbf(v00 - h00, v01 - h01),
                          packbf(v10 - h10, v11 - h11));
}

// ---------------------------------------------------------------------------
// Kernel 1: qkv GEMM (unchanged from round 13 — proven ~12us).
// ---------------------------------------------------------------------------
__device__ __forceinline__ void mma16816(float* d,
                                         unsigned int a0, unsigned int a1,
                                         unsigned int a2, unsigned int a3,
                                         unsigned int b0, unsigned int b1) {
    asm volatile(
        "mma.sync.aligned.m16n8k16.row.col.f32.bf16.bf16.f32 "
        "{%0,%1,%2,%3}, {%4,%5,%6,%7}, {%8,%9}, {%0,%1,%2,%3};"
        : "+f"(d[0]), "+f"(d[1]), "+f"(d[2]), "+f"(d[3])
        : "r"(a0), "r"(a1), "r"(a2), "r"(a3), "r"(b0), "r"(b1));
}

#define SM_QKV_TOT (192 * 68 * 4)

__global__ void __launch_bounds__(256, 2)
qkv_mma_kernel() {
    extern __shared__ char smem[];
    const int tid  = threadIdx.x;
    const int lane = tid & 31;
    const int wid  = tid >> 5;
    const int pw   = wid & 1;
    const int cw   = wid >> 1;
    const int p0   = blockIdx.x * 64;
    const int Tb   = blockIdx.x * 4;

    float acc[2][6][4];
#pragma unroll
    for (int m = 0; m < 2; m++)
#pragma unroll
        for (int n = 0; n < 6; n++)
#pragma unroll
            for (int i = 0; i < 4; i++) acc[m][n][i] = 0.f;

#pragma unroll
    for (int k = 0; k < 4; k++) {
        uint2 bh[6], bl[6];
#pragma unroll
        for (int n = 0; n < 6; n++) {
            int nt = cw * 6 + n;
            bh[n] = g_whf[(nt * 4 + k) * 32 + lane];
            bl[n] = g_wlf[(nt * 4 + k) * 32 + lane];
        }
#pragma unroll
        for (int m = 0; m < 2; m++) {
            size_t ai = ((size_t)(Tb + pw * 2 + m) * 4 + k) * 32 + lane;
            uint4 ah = g_xhf[ai];
            uint4 al = g_xlf[ai];
#pragma unroll
            for (int n = 0; n < 6; n++) {
                mma16816(acc[m][n], ah.x, ah.y, ah.z, ah.w, bh[n].x, bh[n].y);
                mma16816(acc[m][n], al.x, al.y, al.z, al.w, bh[n].x, bh[n].y);
                mma16816(acc[m][n], ah.x, ah.y, ah.z, ah.w, bl[n].x, bl[n].y);
            }
        }
    }

    float* sout = (float*)smem;
    const int posw = pw * 32;
    const int cb   = cw * 48;
    const int r    = lane >> 2;
    const int c2   = (lane & 3) * 2;
#pragma unroll
    for (int m = 0; m < 2; m++)
#pragma unroll
        for (int n = 0; n < 6; n++) {
            int chan = cb + n * 8 + c2;
            int pl   = posw + m * 16 + r;
            sout[chan * 68 + pl]           = acc[m][n][0];
            sout[(chan + 1) * 68 + pl]     = acc[m][n][1];
            sout[chan * 68 + pl + 8]       = acc[m][n][2];
            sout[(chan + 1) * 68 + pl + 8] = acc[m][n][3];
        }
    __syncthreads();

#pragma unroll
    for (int it = 0; it < 12; it++) {
        int j    = it * 256 + tid;
        int chan = j >> 4;
        int f4   = j & 15;
        float4 v = *(const float4*)(sout + chan * 68 + f4 * 4);
        *(float4*)(g_qkv + (size_t)chan * PTOT + p0 + f4 * 4) = v;
    }
}

// ---------------------------------------------------------------------------
// Kernel 2: windowed softmax attention, TD=2 x TH=4 (8 outputs/thread).
// Block (64 w, 4 ty): 1 channel, tile = 2 d-rows x 16 h x 64 w.
// Stages 4 d-planes x 18 h-rows (k/v re-read 2x in d instead of 3x).
// Per tap: t[j] = k + b[j] (3 FADD), per active output: FMUL+EX2+FADD+FFMA.
// All selects compile-time (axis template + unrolled P/R/kw/dd/hh).
// ---------------------------------------------------------------------------
#define RL 66

template<int A>
__device__ __forceinline__ void tap_loop(const float2* __restrict__ skv,
                                         int ty4, int w,
                                         const float* qs, const float* b,
                                         float* den, float* num) {
#pragma unroll
    for (int P = 0; P < 4; P++) {
#pragma unroll
        for (int Rl = 0; Rl < 6; Rl++) {
            const float2* row = skv + (P * 18 + ty4 + Rl) * RL + w;
#pragma unroll
            for (int kw = 0; kw < 3; kw++) {
                float2 kv = row[kw];
                float t0 = kv.x + b[0];
                float t1 = kv.x + b[1];
                float t2 = kv.x + b[2];
#pragma unroll
                for (int dd = 0; dd < 2; dd++) {
                    const int kd = P - dd;
                    if (kd < 0 || kd > 2) continue;
#pragma unroll
                    for (int hh = 0; hh < 4; hh++) {
                        const int kh = Rl - hh;
                        if (kh < 0 || kh > 2) continue;
                        const int j = (A == 0) ? kd : (A == 1) ? kh : kw;
                        const float tj = (j == 0) ? t0 : (j == 1) ? t1 : t2;
                        const int o = dd * 4 + hh;
                        float e = ex2(qs[o] * tj);
                        den[o] += e;
                        num[o] = fmaf(e, kv.y, num[o]);
                    }
                }
            }
        }
    }
}

__global__ void __launch_bounds__(256)
attn_kernel(const float* __restrict__ rel_d,
            const float* __restrict__ rel_h,
            const float* __restrict__ rel_w,
            float* __restrict__ out) {
    __shared__ float2 skv[4][18][RL];    // 38016 B

    const int w   = threadIdx.x;
    const int ty  = threadIdx.y;
    const int tid = ty * 64 + w;
    const int d0  = (blockIdx.x >> 2) * 2;      // 8 d-tiles of 2
    const int h0  = (blockIdx.x & 3) * 16;      // 4 h-tiles of 16
    const int c   = blockIdx.y;

    const float* gk = g_qkv + (size_t)(64  + c) * PTOT;
    const float* gv = g_qkv + (size_t)(128 + c) * PTOT;

    // zero the w-halo columns (cols 0, 65 of each of the 72 rows)
    if (tid < 144) {
        int row = tid >> 1;
        int col = (tid & 1) * 65;
        (&skv[0][0][0])[row * RL + col] = make_float2(0.f, 0.f);
    }
    // stage 72 rows x 64 cols
    for (int idx = tid; idx < 72 * 64; idx += 256) {
        int row = idx >> 6;            // 0..71
        int col = idx & 63;
        int P   = row / 18;
        int R   = row - P * 18;
        int nd  = d0 + P - 1;
        int nh  = h0 + R - 1;
        float kk = 0.f, vv = 0.f;
        if ((unsigned)nd < (unsigned)DD && (unsigned)nh < (unsigned)HH) {
            int g = (nd << 12) + (nh << 6) + col;
            kk = gk[g];
            vv = gv[g];
        }
        skv[P][R][col + 1] = make_float2(kk, vv);
    }
    __syncthreads();

    const int ty4 = ty * 4;

    float qs[8];
#pragma unroll
    for (int dd = 0; dd < 2; dd++)
#pragma unroll
        for (int hh = 0; hh < 4; hh++) {
            int p = ((d0 + dd) << 12) + ((h0 + ty4 + hh) << 6) + w;
            qs[dd * 4 + hh] = g_qkv[(size_t)c * PTOT + p] * LOG2E;
        }

    int axis;
    const float* bp;
    if (c < C3)          { axis = 0; bp = rel_d + c * 3; }
    else if (c < 2 * C3) { axis = 1; bp = rel_h + (c - C3) * 3; }
    else                 { axis = 2; bp = rel_w + (c - 2 * C3) * 3; }
    float b[3] = {bp[0], bp[1], bp[2]};

    float den[8] = {0.f, 0.f, 0.f, 0.f, 0.f, 0.f, 0.f, 0.f};
    float num[8] = {0.f, 0.f, 0.f, 0.f, 0.f, 0.f, 0.f, 0.f};
    const float2* base = &skv[0][0][0];
    if (axis == 0)      tap_loop<0>(base, ty4, w, qs, b, den, num);
    else if (axis == 1) tap_loop<1>(base, ty4, w, qs, b, den, num);
    else                tap_loop<2>(base, ty4, w, qs, b, den, num);

#pragma unroll
    for (int dd = 0; dd < 2; dd++)
#pragma unroll
        for (int hh = 0; hh < 4; hh++) {
            int p = ((d0 + dd) << 12) + ((h0 + ty4 + hh) << 6) + w;
            int o = dd * 4 + hh;
            out[(size_t)c * PTOT + p] = __fdividef(num[o], den[o]);
        }
}

// ---------------------------------------------------------------------------
extern "C" void kernel_launch(void* const* d_in, const int* in_sizes, int n_in,
                              void* d_out, int out_size) {
    const float* x     = (const float*)d_in[0];
    const float* wq    = (const float*)d_in[1];
    const float* wk    = (const float*)d_in[2];
    const float* wv    = (const float*)d_in[3];
    const float* rel_d = (const float*)d_in[4];
    const float* rel_h = (const float*)d_in[5];
    const float* rel_w = (const float*)d_in[6];
    float* out = (float*)d_out;

    prep_w_kernel<<<12, 256>>>(wq, wk, wv);
    prep_x_kernel<<<PTOT / 64, 256>>>(x);

    cudaFuncSetAttribute(qkv_mma_kernel,
                         cudaFuncAttributeMaxDynamicSharedMemorySize, SM_QKV_TOT);
    qkv_mma_kernel<<<PTOT / 64, 256, SM_QKV_TOT>>>();

    dim3 agrid((DD / 2) * (HH / 16), 64);   // (32, 64)
    dim3 ablock(WW, 4);
    attn_kernel<<<agrid, ablock>>>(rel_d, rel_h, rel_w, out);
}

// round 15
// speedup vs baseline: 1.0588x; 1.0588x over previous
#include <cuda_runtime.h>
#include <cuda_bf16.h>
#include <cstdint>

#define DD    16
#define HH    64
#define WW    64
#define PTOT  (DD*HH*WW)      // 65536
#define C3    21
#define LOG2E 1.4426950408889634f

// scratch: rows 0-63 = q, 64-127 = k, 128-191 = v
__device__ float g_qkv[192 * PTOT];

// fragment-major operands for m16n8k16 row.col
__device__ __align__(16) uint4 g_xhf[(PTOT / 16) * 4 * 32];
__device__ __align__(16) uint4 g_xlf[(PTOT / 16) * 4 * 32];
__device__ __align__(16) uint2 g_whf[24 * 4 * 32];
__device__ __align__(16) uint2 g_wlf[24 * 4 * 32];

__device__ __forceinline__ float ex2(float x) {
    float r;
    asm("ex2.approx.ftz.f32 %0, %1;" : "=f"(r) : "f"(x));
    return r;
}

__device__ __forceinline__ unsigned int packbf(float a, float b) {
    __nv_bfloat162 h = __floats2bfloat162_rn(a, b);
    return *(unsigned int*)&h;
}

// 4-byte cp.async (ca): dst only needs 4B alignment -> can hit float2 fields
__device__ __forceinline__ void cp4(unsigned int dst, const void* src) {
    asm volatile("cp.async.ca.shared.global [%0], [%1], 4;" :: "r"(dst), "l"(src) : "memory");
}
// zero-fill variant (src-size = 0): no bytes read
__device__ __forceinline__ void cp4z(unsigned int dst, const void* src) {
    asm volatile("cp.async.ca.shared.global [%0], [%1], 4, 0;" :: "r"(dst), "l"(src) : "memory");
}
__device__ __forceinline__ void cp_commit() {
    asm volatile("cp.async.commit_group;" ::: "memory");
}
template<int N>
__device__ __forceinline__ void cp_wait() {
    asm volatile("cp.async.wait_group %0;" :: "n"(N) : "memory");
}

// ---------------------------------------------------------------------------
// Prep A: x (fp32 [ci][pos]) -> fragment-major bf16 hi/lo (proven).
// ---------------------------------------------------------------------------
__global__ void __launch_bounds__(256)
prep_x_kernel(const float* __restrict__ x) {
    __shared__ float tile[64 * 65];
    const int tid = threadIdx.x;
    const int p0  = blockIdx.x * 64;

#pragma unroll
    for (int i = 0; i < 16; i++) {
        int j  = i * 256 + tid;
        int ci = j >> 6, p = j & 63;
        tile[ci * 65 + p] = x[ci * PTOT + p0 + p];
    }
    __syncthreads();

#pragma unroll
    for (int i = 0; i < 2; i++) {
        int j    = i * 256 + tid;
        int lane = j & 31;
        int k    = (j >> 5) & 3;
        int lt   = j >> 7;
        int r    = lane >> 2;
        int kc   = k * 16 + (lane & 3) * 2;
        int pa   = lt * 16 + r;
        int pb   = pa + 8;

        float v00 = tile[kc * 65 + pa],       v01 = tile[(kc + 1) * 65 + pa];
        float v10 = tile[kc * 65 + pb],       v11 = tile[(kc + 1) * 65 + pb];
        float v20 = tile[(kc + 8) * 65 + pa], v21 = tile[(kc + 9) * 65 + pa];
        float v30 = tile[(kc + 8) * 65 + pb], v31 = tile[(kc + 9) * 65 + pb];

        float h00 = __bfloat162float(__float2bfloat16(v00));
        float h01 = __bfloat162float(__float2bfloat16(v01));
        float h10 = __bfloat162float(__float2bfloat16(v10));
        float h11 = __bfloat162float(__float2bfloat16(v11));
        float h20 = __bfloat162float(__float2bfloat16(v20));
        float h21 = __bfloat162float(__float2bfloat16(v21));
        float h30 = __bfloat162float(__float2bfloat16(v30));
        float h31 = __bfloat162float(__float2bfloat16(v31));

        size_t idx = ((size_t)(p0 / 16 + lt) * 4 + k) * 32 + lane;
        g_xhf[idx] = make_uint4(packbf(h00, h01), packbf(h10, h11),
                                packbf(h20, h21), packbf(h30, h31));
        g_xlf[idx] = make_uint4(packbf(v00 - h00, v01 - h01),
                                packbf(v10 - h10, v11 - h11),
                                packbf(v20 - h20, v21 - h21),
                                packbf(v30 - h30, v31 - h31));
    }
}

// ---------------------------------------------------------------------------
// Prep B: W -> fragment-major bf16 hi/lo (proven).
// ---------------------------------------------------------------------------
__global__ void prep_w_kernel(const float* __restrict__ wq,
                              const float* __restrict__ wk,
                              const float* __restrict__ wv) {
    int j = blockIdx.x * 256 + threadIdx.x;
    if (j >= 24 * 4 * 32) return;
    int lane = j & 31;
    int k    = (j >> 5) & 3;
    int nt   = j >> 7;
    int c    = nt * 8 + (lane >> 2);
    int kc   = k * 16 + (lane & 3) * 2;

    const float* src;
    int cr = c;
    if (c < 64)       { src = wq; }
    else if (c < 128) { src = wk; cr = c - 64; }
    else              { src = wv; cr = c - 128; }

    float v00 = src[cr * 64 + kc],     v01 = src[cr * 64 + kc + 1];
    float v10 = src[cr * 64 + kc + 8], v11 = src[cr * 64 + kc + 9];

    float h00 = __bfloat162float(__float2bfloat16(v00));
    float h01 = __bfloat162float(__float2bfloat16(v01));
    float h10 = __bfloat162float(__float2bfloat16(v10));
    float h11 = __bfloat162float(__float2bfloat16(v11));

    g_whf[j] = make_uint2(packbf(h00, h01), packbf(h10, h11));
    g_wlf[j] = make_uint2(packbf(v00 - h00, v01 - h01),
                          packbf(v10 - h10, v11 - h11));
}

// ---------------------------------------------------------------------------
// Kernel 1: qkv GEMM (unchanged — proven ~12us).
// ---------------------------------------------------------------------------
__device__ __forceinline__ void mma16816(float* d,
                                         unsigned int a0, unsigned int a1,
                                         unsigned int a2, unsigned int a3,
                                         unsigned int b0, unsigned int b1) {
    asm volatile(
        "mma.sync.aligned.m16n8k16.row.col.f32.bf16.bf16.f32 "
        "{%0,%1,%2,%3}, {%4,%5,%6,%7}, {%8,%9}, {%0,%1,%2,%3};"
        : "+f"(d[0]), "+f"(d[1]), "+f"(d[2]), "+f"(d[3])
        : "r"(a0), "r"(a1), "r"(a2), "r"(a3), "r"(b0), "r"(b1));
}

#define SM_QKV_TOT (192 * 68 * 4)

__global__ void __launch_bounds__(256, 2)
qkv_mma_kernel() {
    extern __shared__ char smem[];
    const int tid  = threadIdx.x;
    const int lane = tid & 31;
    const int wid  = tid >> 5;
    const int pw   = wid & 1;
    const int cw   = wid >> 1;
    const int p0   = blockIdx.x * 64;
    const int Tb   = blockIdx.x * 4;

    float acc[2][6][4];
#pragma unroll
    for (int m = 0; m < 2; m++)
#pragma unroll
        for (int n = 0; n < 6; n++)
#pragma unroll
            for (int i = 0; i < 4; i++) acc[m][n][i] = 0.f;

#pragma unroll
    for (int k = 0; k < 4; k++) {
        uint2 bh[6], bl[6];
#pragma unroll
        for (int n = 0; n < 6; n++) {
            int nt = cw * 6 + n;
            bh[n] = g_whf[(nt * 4 + k) * 32 + lane];
            bl[n] = g_wlf[(nt * 4 + k) * 32 + lane];
        }
#pragma unroll
        for (int m = 0; m < 2; m++) {
            size_t ai = ((size_t)(Tb + pw * 2 + m) * 4 + k) * 32 + lane;
            uint4 ah = g_xhf[ai];
            uint4 al = g_xlf[ai];
#pragma unroll
            for (int n = 0; n < 6; n++) {
                mma16816(acc[m][n], ah.x, ah.y, ah.z, ah.w, bh[n].x, bh[n].y);
                mma16816(acc[m][n], al.x, al.y, al.z, al.w, bh[n].x, bh[n].y);
                mma16816(acc[m][n], ah.x, ah.y, ah.z, ah.w, bl[n].x, bl[n].y);
            }
        }
    }

    float* sout = (float*)smem;
    const int posw = pw * 32;
    const int cb   = cw * 48;
    const int r    = lane >> 2;
    const int c2   = (lane & 3) * 2;
#pragma unroll
    for (int m = 0; m < 2; m++)
#pragma unroll
        for (int n = 0; n < 6; n++) {
            int chan = cb + n * 8 + c2;
            int pl   = posw + m * 16 + r;
            sout[chan * 68 + pl]           = acc[m][n][0];
            sout[(chan + 1) * 68 + pl]     = acc[m][n][1];
            sout[chan * 68 + pl + 8]       = acc[m][n][2];
            sout[(chan + 1) * 68 + pl + 8] = acc[m][n][3];
        }
    __syncthreads();

#pragma unroll
    for (int it = 0; it < 12; it++) {
        int j    = it * 256 + tid;
        int chan = j >> 4;
        int f4   = j & 15;
        float4 v = *(const float4*)(sout + chan * 68 + f4 * 4);
        *(float4*)(g_qkv + (size_t)chan * PTOT + p0 + f4 * 4) = v;
    }
}

// ---------------------------------------------------------------------------
// Kernel 2: windowed softmax attention — R13 compute (TH=4, proven) +
// 4 channels per block with DOUBLE-BUFFERED cp.async staging so channel i+1's
// k/v stream in while channel i computes. Only the prologue stage is exposed.
// ---------------------------------------------------------------------------
#define RL 66
#define CH_F2 (54 * RL)          // float2 per channel buffer

template<int A>
__device__ __forceinline__ void tap_loop(const float2* __restrict__ skv,
                                         int hb, int w,
                                         const float* qs, const float (*qb)[3],
                                         float* den, float* num) {
#pragma unroll
    for (int kd = 0; kd < 3; kd++) {
#pragma unroll
        for (int R = 0; R < 6; R++) {
            const float2* row = skv + (kd * 18 + hb + R) * RL + w;
#pragma unroll
            for (int kw = 0; kw < 3; kw++) {
                float2 kv = row[kw];
#pragma unroll
                for (int o = 0; o < 4; o++) {
                    if (R >= o && R <= o + 2) {
                        const int j = (A == 0) ? kd : (A == 1) ? (R - o) : kw;
                        float e = ex2(fmaf(qs[o], kv.x, qb[o][j]));
                        den[o] += e;
                        num[o] = fmaf(e, kv.y, num[o]);
                    }
                }
            }
        }
    }
}

// stage one channel's k/v into buffer (cp.async, not yet committed)
__device__ __forceinline__ void stage_ch(unsigned int sbuf, int c, int d, int h0,
                                         int tid) {
    const float* gk = g_qkv + (size_t)(64 + c) * PTOT;
    const float* gv = g_qkv + (size_t)(128 + c) * PTOT;
    for (int idx = tid; idx < 54 * 64; idx += 256) {
        int row = idx >> 6;
        int col = idx & 63;
        int kd  = row / 18;
        int R   = row - kd * 18;
        int nd  = d + kd - 1;
        int nh  = h0 + R - 1;
        unsigned int dst = sbuf + (unsigned int)(row * RL + col + 1) * 8;
        if ((unsigned)nd < (unsigned)DD && (unsigned)nh < (unsigned)HH) {
            int g = (nd << 12) + (nh << 6) + col;
            cp4(dst,     gk + g);
            cp4(dst + 4, gv + g);
        } else {
            cp4z(dst,     gk);
            cp4z(dst + 4, gk);
        }
    }
}

__global__ void __launch_bounds__(256)
attn_kernel(const float* __restrict__ rel_d,
            const float* __restrict__ rel_h,
            const float* __restrict__ rel_w,
            float* __restrict__ out) {
    extern __shared__ float2 skv[];      // [2][54][RL] = 57024 B

    const int w   = threadIdx.x;
    const int ty  = threadIdx.y;
    const int tid = ty * 64 + w;
    const int d   = blockIdx.x >> 2;
    const int h0  = (blockIdx.x & 3) * 16;
    const int c0  = blockIdx.y * 4;

    const unsigned int sb = (unsigned int)__cvta_generic_to_shared(skv);

    // zero w-halo cols (0, 65) of both buffers — never overwritten by staging
    if (tid < 216) {
        int b   = tid / 108;
        int r2  = tid - b * 108;
        int row = r2 >> 1;
        int col = (r2 & 1) * 65;
        skv[b * CH_F2 + row * RL + col] = make_float2(0.f, 0.f);
    }

    // prologue: stage channel 0 into buffer 0
    stage_ch(sb, c0, d, h0, tid);
    cp_commit();

    const int hb = ty * 4;

#pragma unroll
    for (int i = 0; i < 4; i++) {
        if (i < 3) {
            stage_ch(sb + ((i + 1) & 1) * (CH_F2 * 8), c0 + i + 1, d, h0, tid);
            cp_commit();
            cp_wait<1>();
        } else {
            cp_wait<0>();
        }
        __syncthreads();

        const int c = c0 + i;
        const float2* base = skv + (i & 1) * CH_F2;

        const int p0 = (d << 12) + ((h0 + hb) << 6) + w;
        float qs[4];
#pragma unroll
        for (int o = 0; o < 4; o++)
            qs[o] = g_qkv[(size_t)c * PTOT + p0 + o * 64] * LOG2E;

        int axis;
        const float* bp;
        if (c < C3)          { axis = 0; bp = rel_d + c * 3; }
        else if (c < 2 * C3) { axis = 1; bp = rel_h + (c - C3) * 3; }
        else                 { axis = 2; bp = rel_w + (c - 2 * C3) * 3; }
        float qb[4][3];
#pragma unroll
        for (int o = 0; o < 4; o++)
#pragma unroll
            for (int j = 0; j < 3; j++)
                qb[o][j] = qs[o] * bp[j];

        float den[4] = {0.f, 0.f, 0.f, 0.f};
        float num[4] = {0.f, 0.f, 0.f, 0.f};
        if (axis == 0)      tap_loop<0>(base, hb, w, qs, qb, den, num);
        else if (axis == 1) tap_loop<1>(base, hb, w, qs, qb, den, num);
        else                tap_loop<2>(base, hb, w, qs, qb, den, num);

#pragma unroll
        for (int o = 0; o < 4; o++)
            out[(size_t)c * PTOT + p0 + o * 64] = __fdividef(num[o], den[o]);

        __syncthreads();   // buffer (i&1) free before it is restaged
    }
}

// ---------------------------------------------------------------------------
extern "C" void kernel_launch(void* const* d_in, const int* in_sizes, int n_in,
                              void* d_out, int out_size) {
    const float* x     = (const float*)d_in[0];
    const float* wq    = (const float*)d_in[1];
    const float* wk    = (const float*)d_in[2];
    const float* wv    = (const float*)d_in[3];
    const float* rel_d = (const float*)d_in[4];
    const float* rel_h = (const float*)d_in[5];
    const float* rel_w = (const float*)d_in[6];
    float* out = (float*)d_out;

    prep_w_kernel<<<12, 256>>>(wq, wk, wv);
    prep_x_kernel<<<PTOT / 64, 256>>>(x);

    cudaFuncSetAttribute(qkv_mma_kernel,
                         cudaFuncAttributeMaxDynamicSharedMemorySize, SM_QKV_TOT);
    qkv_mma_kernel<<<PTOT / 64, 256, SM_QKV_TOT>>>();

    const int attn_smem = 2 * CH_F2 * (int)sizeof(float2);   // 57024
    cudaFuncSetAttribute(attn_kernel,
                         cudaFuncAttributeMaxDynamicSharedMemorySize, attn_smem);
    dim3 agrid(DD * (HH / 16), 16);   // (64, 16), 4 channels per block
    dim3 ablock(WW, 4);
    attn_kernel<<<agrid, ablock, attn_smem>>>(rel_d, rel_h, rel_w, out);
}